// round 1
// baseline (speedup 1.0000x reference)
#include <cuda_runtime.h>
#include <cuda_bf16.h>
#include <math.h>

// ---------------------------------------------------------------------------
// Model dims (compile-time constants)
// ---------------------------------------------------------------------------
#define DIM   1024
#define FFDIM 4096
#define VOC   32000
#define SEQ   1024
#define BATCH 2
#define MTOK  (BATCH * SEQ)   // 2048 token rows

// Flat offsets into blocks (fp32 elements)
#define OFF_EMBED 0LL
#define LAYER0_OFF 32768000LL              // V*D
#define LAYER_STRIDE 16777216LL            // 4*D*D + 3*FF*D
#define OFF_LM (LAYER0_OFF + 2*LAYER_STRIDE) // 66322432

// ---------------------------------------------------------------------------
// Scratch (device globals; allocation inside kernel_launch is forbidden)
// ---------------------------------------------------------------------------
__device__ float g_h [MTOK * DIM];     // hidden state
__device__ float g_q [MTOK * DIM];
__device__ float g_k [MTOK * DIM];
__device__ float g_v [MTOK * DIM];
__device__ float g_s [BATCH * SEQ * SEQ]; // attention scores
__device__ float g_a [MTOK * DIM];     // attention output
__device__ float g_g [MTOK * FFDIM];   // gate (then silu(g)*u)
__device__ float g_u [MTOK * FFDIM];   // up

// ---------------------------------------------------------------------------
// GEMM: C = alpha * A @ op(B) (+ R)
//   NT=true : B is [N,K] row-major (C += A·B^T)  -- all weight matmuls, QK^T
//   NT=false: B is [K,N] row-major (C += A·B)    -- attn @ V
// All dims multiples of tile sizes (M%128==0, N%128==0, K%16==0).
// ---------------------------------------------------------------------------
template <bool NT>
__global__ __launch_bounds__(256, 2)
void gemm_kernel(const float* __restrict__ A, const float* __restrict__ B,
                 const float* R, float* C,
                 int M, int N, int K, float alpha,
                 long long sA, long long sB, long long sC)
{
    const int BM = 128, BN = 128, BK = 16;
    __shared__ float As[BK][BM + 4];
    __shared__ float Bs[BK][BN + 4];

    const long long bz = blockIdx.z;
    A += bz * sA;  B += bz * sB;  C += bz * sC;
    const float* Rp = R ? (R + bz * sC) : nullptr;

    const int tid  = threadIdx.x;
    const int row0 = blockIdx.y * BM;
    const int col0 = blockIdx.x * BN;

    // A / NT-B loaders: 128 rows x 16 k, float4 along K
    const int ar = tid >> 2;             // 0..63 (two rows: +0, +64)
    const int ak = (tid & 3) << 2;       // 0,4,8,12
    // NN-B loader: 16 rows x 128 cols, float4 along N
    const int br = tid >> 5;             // 0..7 (two rows: +0, +8)
    const int bc = (tid & 31) << 2;      // 0..124

    const int ty = tid >> 4;             // 0..15
    const int tx = tid & 15;

    float acc[8][8];
#pragma unroll
    for (int i = 0; i < 8; i++)
#pragma unroll
        for (int j = 0; j < 8; j++) acc[i][j] = 0.0f;

    for (int k0 = 0; k0 < K; k0 += BK) {
#pragma unroll
        for (int i = 0; i < 2; i++) {
            int r = ar + i * 64;
            float4 va = *(const float4*)(A + (long long)(row0 + r) * K + k0 + ak);
            As[ak + 0][r] = va.x; As[ak + 1][r] = va.y;
            As[ak + 2][r] = va.z; As[ak + 3][r] = va.w;
        }
        if (NT) {
#pragma unroll
            for (int i = 0; i < 2; i++) {
                int r = ar + i * 64;
                float4 vb = *(const float4*)(B + (long long)(col0 + r) * K + k0 + ak);
                Bs[ak + 0][r] = vb.x; Bs[ak + 1][r] = vb.y;
                Bs[ak + 2][r] = vb.z; Bs[ak + 3][r] = vb.w;
            }
        } else {
#pragma unroll
            for (int i = 0; i < 2; i++) {
                int r = br + i * 8;
                float4 vb = *(const float4*)(B + (long long)(k0 + r) * N + col0 + bc);
                *(float4*)&Bs[r][bc] = vb;
            }
        }
        __syncthreads();

#pragma unroll
        for (int k = 0; k < BK; k++) {
            float ra[8], rb[8];
            *(float4*)&ra[0] = *(const float4*)&As[k][ty * 8];
            *(float4*)&ra[4] = *(const float4*)&As[k][ty * 8 + 4];
            *(float4*)&rb[0] = *(const float4*)&Bs[k][tx * 8];
            *(float4*)&rb[4] = *(const float4*)&Bs[k][tx * 8 + 4];
#pragma unroll
            for (int i = 0; i < 8; i++)
#pragma unroll
                for (int j = 0; j < 8; j++)
                    acc[i][j] = fmaf(ra[i], rb[j], acc[i][j]);
        }
        __syncthreads();
    }

#pragma unroll
    for (int i = 0; i < 8; i++) {
        long long crow = row0 + ty * 8 + i;
#pragma unroll
        for (int j = 0; j < 8; j += 4) {
            long long idx = crow * (long long)N + col0 + tx * 8 + j;
            float4 v;
            v.x = acc[i][j + 0] * alpha;
            v.y = acc[i][j + 1] * alpha;
            v.z = acc[i][j + 2] * alpha;
            v.w = acc[i][j + 3] * alpha;
            if (Rp) {
                float4 r4 = *(const float4*)(Rp + idx);
                v.x += r4.x; v.y += r4.y; v.z += r4.z; v.w += r4.w;
            }
            *(float4*)(C + idx) = v;
        }
    }
}

// ---------------------------------------------------------------------------
// Embedding gather: h[bs,:] = embed[ids[bs],:]
// ---------------------------------------------------------------------------
__global__ void embed_kernel(const int* __restrict__ ids,
                             const float* __restrict__ embed,
                             float* __restrict__ h)
{
    int bs = blockIdx.x;
    long long tok = ids[bs];
    const float4* src = (const float4*)(embed + tok * DIM);
    float4* dst = (float4*)(h + (long long)bs * DIM);
    dst[threadIdx.x] = src[threadIdx.x];   // 256 threads x float4 = 1024 floats
}

// ---------------------------------------------------------------------------
// RoPE (in place on q and k). block = one (b,s) row, 512 threads.
// ---------------------------------------------------------------------------
__global__ void rope_kernel(float* __restrict__ q, float* __restrict__ k)
{
    int bs = blockIdx.x;
    int s  = bs & (SEQ - 1);
    int d  = threadIdx.x;                       // 0..511
    float freq = expf(-logf(10000.0f) * ((float)d / 512.0f));
    float ang  = (float)s * freq;
    float sn, cs;
    sincosf(ang, &sn, &cs);

    float* rq = q + (long long)bs * DIM;
    float x1 = rq[d], x2 = rq[d + 512];
    rq[d]       = x1 * cs - x2 * sn;
    rq[d + 512] = x2 * cs + x1 * sn;

    float* rk = k + (long long)bs * DIM;
    x1 = rk[d]; x2 = rk[d + 512];
    rk[d]       = x1 * cs - x2 * sn;
    rk[d + 512] = x2 * cs + x1 * sn;
}

// ---------------------------------------------------------------------------
// Row softmax over rows of length 1024. block = one row, 256 threads.
// ---------------------------------------------------------------------------
__global__ void softmax_kernel(float* __restrict__ Sm)
{
    __shared__ float red[256];
    float* row = Sm + (long long)blockIdx.x * SEQ;
    int t = threadIdx.x;
    float4 v = ((float4*)row)[t];

    float m = fmaxf(fmaxf(v.x, v.y), fmaxf(v.z, v.w));
    red[t] = m;
    __syncthreads();
    for (int w = 128; w > 0; w >>= 1) {
        if (t < w) red[t] = fmaxf(red[t], red[t + w]);
        __syncthreads();
    }
    m = red[0];
    __syncthreads();

    float e0 = expf(v.x - m), e1 = expf(v.y - m);
    float e2 = expf(v.z - m), e3 = expf(v.w - m);
    red[t] = e0 + e1 + e2 + e3;
    __syncthreads();
    for (int w = 128; w > 0; w >>= 1) {
        if (t < w) red[t] += red[t + w];
        __syncthreads();
    }
    float inv = 1.0f / red[0];
    ((float4*)row)[t] = make_float4(e0 * inv, e1 * inv, e2 * inv, e3 * inv);
}

// ---------------------------------------------------------------------------
// t = silu(g) * u, written into g
// ---------------------------------------------------------------------------
__global__ void silu_mul_kernel(float* __restrict__ g, const float* __restrict__ u)
{
    long long i = (long long)blockIdx.x * blockDim.x + threadIdx.x;
    float x = g[i];
    float s = 1.0f / (1.0f + expf(-x));
    g[i] = x * s * u[i];
}

// ---------------------------------------------------------------------------
// Host launch helpers
// ---------------------------------------------------------------------------
static void launch_gemm_nt(const float* A, const float* B, const float* R, float* C,
                           int M, int N, int K, float alpha, int batch,
                           long long sA, long long sB, long long sC)
{
    dim3 grid(N / 128, M / 128, batch);
    gemm_kernel<true><<<grid, 256>>>(A, B, R, C, M, N, K, alpha, sA, sB, sC);
}
static void launch_gemm_nn(const float* A, const float* B, const float* R, float* C,
                           int M, int N, int K, float alpha, int batch,
                           long long sA, long long sB, long long sC)
{
    dim3 grid(N / 128, M / 128, batch);
    gemm_kernel<false><<<grid, 256>>>(A, B, R, C, M, N, K, alpha, sA, sB, sC);
}

extern "C" void kernel_launch(void* const* d_in, const int* in_sizes, int n_in,
                              void* d_out, int out_size)
{
    (void)in_sizes; (void)n_in; (void)out_size;
    const int*   ids    = (const int*)d_in[0];
    const float* blocks = (const float*)d_in[1];
    float*       out    = (float*)d_out;

    float *h, *q, *k, *v, *s, *a, *gt, *up;
    cudaGetSymbolAddress((void**)&h,  g_h);
    cudaGetSymbolAddress((void**)&q,  g_q);
    cudaGetSymbolAddress((void**)&k,  g_k);
    cudaGetSymbolAddress((void**)&v,  g_v);
    cudaGetSymbolAddress((void**)&s,  g_s);
    cudaGetSymbolAddress((void**)&a,  g_a);
    cudaGetSymbolAddress((void**)&gt, g_g);
    cudaGetSymbolAddress((void**)&up, g_u);

    const float* embed = blocks + OFF_EMBED;
    const float  scale = 1.0f / 32.0f;   // 1/sqrt(1024)
    const long long SD = (long long)SEQ * DIM;      // per-batch q/k/v stride
    const long long SS = (long long)SEQ * SEQ;      // per-batch score stride

    // h = embed[ids]
    embed_kernel<<<MTOK, 256>>>(ids, embed, h);

    for (int l = 0; l < 2; l++) {
        const float* Wq = blocks + LAYER0_OFF + (long long)l * LAYER_STRIDE;
        const float* Wk = Wq + (long long)DIM * DIM;
        const float* Wv = Wk + (long long)DIM * DIM;
        const float* Wo = Wv + (long long)DIM * DIM;
        const float* Wg = Wo + (long long)DIM * DIM;
        const float* Wu = Wg + (long long)FFDIM * DIM;
        const float* Wd = Wu + (long long)FFDIM * DIM;

        // q/k/v projections
        launch_gemm_nt(h, Wq, nullptr, q, MTOK, DIM, DIM, 1.0f, 1, 0, 0, 0);
        launch_gemm_nt(h, Wk, nullptr, k, MTOK, DIM, DIM, 1.0f, 1, 0, 0, 0);
        launch_gemm_nt(h, Wv, nullptr, v, MTOK, DIM, DIM, 1.0f, 1, 0, 0, 0);
        // rope(q), rope(k)
        rope_kernel<<<MTOK, 512>>>(q, k);
        // scores = scale * q @ k^T   (batched over 2)
        launch_gemm_nt(q, k, nullptr, s, SEQ, SEQ, DIM, scale, BATCH, SD, SD, SS);
        // softmax rows
        softmax_kernel<<<BATCH * SEQ, 256>>>(s);
        // a = attn @ v               (batched over 2, NN)
        launch_gemm_nn(s, v, nullptr, a, SEQ, DIM, SEQ, 1.0f, BATCH, SS, SD, SD);
        // h = a @ Wo^T + h
        launch_gemm_nt(a, Wo, h, h, MTOK, DIM, DIM, 1.0f, 1, 0, 0, 0);
        // MLP
        launch_gemm_nt(h, Wg, nullptr, gt, MTOK, FFDIM, DIM, 1.0f, 1, 0, 0, 0);
        launch_gemm_nt(h, Wu, nullptr, up, MTOK, FFDIM, DIM, 1.0f, 1, 0, 0, 0);
        silu_mul_kernel<<<(MTOK * FFDIM) / 256, 256>>>(gt, up);
        launch_gemm_nt(gt, Wd, h, h, MTOK, DIM, FFDIM, 1.0f, 1, 0, 0, 0);
    }

    // logits = h @ lm^T
    const float* Wlm = blocks + OFF_LM;
    launch_gemm_nt(h, Wlm, nullptr, out, MTOK, VOC, DIM, 1.0f, 1, 0, 0, 0);
}

// round 3
// speedup vs baseline: 2.3753x; 2.3753x over previous
#include <cuda_runtime.h>
#include <cuda_bf16.h>
#include <math.h>
#include <stdint.h>

// ---------------------------------------------------------------------------
// Model dims
// ---------------------------------------------------------------------------
#define DIM   1024
#define FFDIM 4096
#define VOC   32000
#define SEQ   1024
#define BATCH 2
#define MTOK  (BATCH * SEQ)

#define LAYER0_OFF   32768000LL
#define LAYER_STRIDE 16777216LL
#define OFF_LM       (LAYER0_OFF + 2*LAYER_STRIDE)

// ---------------------------------------------------------------------------
// Scratch
// ---------------------------------------------------------------------------
__device__ float g_h  [MTOK * DIM];
__device__ float g_qkv[MTOK * 3 * DIM];
__device__ float g_vt [BATCH * DIM * SEQ];
__device__ float g_s  [BATCH * SEQ * SEQ];
__device__ float g_a  [MTOK * DIM];
__device__ float g_gu [MTOK * 2 * FFDIM];
__device__ float g_t  [MTOK * FFDIM];

// ---------------------------------------------------------------------------
// tf32 helpers (portable mma.sync path — tcgen05 unavailable on this target)
// ---------------------------------------------------------------------------
__device__ __forceinline__ uint32_t f2tf32(float x) {
    uint32_t r;
    asm("cvt.rna.tf32.f32 %0, %1;" : "=r"(r) : "f"(x));
    return r;
}

__device__ __forceinline__ void mma16n8k8(float c[4], const uint32_t a[4],
                                          const uint32_t b[2]) {
    asm volatile(
        "mma.sync.aligned.m16n8k8.row.col.f32.tf32.tf32.f32 "
        "{%0,%1,%2,%3}, {%4,%5,%6,%7}, {%8,%9}, {%0,%1,%2,%3};"
        : "+f"(c[0]), "+f"(c[1]), "+f"(c[2]), "+f"(c[3])
        : "r"(a[0]), "r"(a[1]), "r"(a[2]), "r"(a[3]), "r"(b[0]), "r"(b[1]));
}

// ---------------------------------------------------------------------------
// tf32 GEMM: C[M,N] = alpha * A[M,K] @ B[N,K]^T (+ R)
// BM=BN=128, BK=16. 256 threads, 8 warps (2 M x 4 N), warp tile 64x32.
// Double-buffered smem, k-major [BK][BM+8] (pad 8 => conflict-free frag loads).
// ---------------------------------------------------------------------------
#define BM 128
#define BN 128
#define BK 16
#define PAD 8

__global__ __launch_bounds__(256, 2)
void tf32_gemm(const float* __restrict__ A, int lda, long long sAz,
               const float* __restrict__ B, int ldb, long long sBz,
               float* __restrict__ C, int ldc, long long sCz,
               const float* __restrict__ R, int K, float alpha)
{
    __shared__ uint32_t As[2][BK][BM + PAD];
    __shared__ uint32_t Bs[2][BK][BN + PAD];

    const int tid  = threadIdx.x;
    const int warp = tid >> 5, lane = tid & 31;
    const int wm = warp & 1;          // 0..1  (M)
    const int wn = warp >> 1;         // 0..3  (N)
    const int g  = lane >> 2;         // 0..7
    const int tg = lane & 3;          // 0..3

    const long long bz = blockIdx.z;
    A += bz * sAz;  B += bz * sBz;  C += bz * sCz;
    const float* Rp = R ? (R + bz * sCz) : nullptr;
    const int row0 = blockIdx.y * BM;
    const int col0 = blockIdx.x * BN;

    // global loaders: 128 rows x 16k, two rows per thread, float4 along K
    const int ar = tid >> 2;              // 0..63
    const int ak = (tid & 3) << 2;        // 0,4,8,12
    const float* Ag0 = A + (long long)(row0 + ar) * lda + ak;
    const float* Ag1 = A + (long long)(row0 + ar + 64) * lda + ak;
    const float* Bg0 = B + (long long)(col0 + ar) * ldb + ak;
    const float* Bg1 = B + (long long)(col0 + ar + 64) * ldb + ak;

    float4 va0, va1, vb0, vb1;

    auto gload = [&](int k0) {
        va0 = *(const float4*)(Ag0 + k0);
        va1 = *(const float4*)(Ag1 + k0);
        vb0 = *(const float4*)(Bg0 + k0);
        vb1 = *(const float4*)(Bg1 + k0);
    };
    auto sstore = [&](int buf) {
        const float* f;
        f = (const float*)&va0;
#pragma unroll
        for (int j = 0; j < 4; j++) As[buf][ak + j][ar]      = f2tf32(f[j]);
        f = (const float*)&va1;
#pragma unroll
        for (int j = 0; j < 4; j++) As[buf][ak + j][ar + 64] = f2tf32(f[j]);
        f = (const float*)&vb0;
#pragma unroll
        for (int j = 0; j < 4; j++) Bs[buf][ak + j][ar]      = f2tf32(f[j]);
        f = (const float*)&vb1;
#pragma unroll
        for (int j = 0; j < 4; j++) Bs[buf][ak + j][ar + 64] = f2tf32(f[j]);
    };

    float acc[4][4][4];
#pragma unroll
    for (int mi = 0; mi < 4; mi++)
#pragma unroll
        for (int ni = 0; ni < 4; ni++)
#pragma unroll
            for (int j = 0; j < 4; j++) acc[mi][ni][j] = 0.0f;

    gload(0);
    sstore(0);
    __syncthreads();

    const int NK = K / BK;
    for (int it = 0; it < NK; it++) {
        if (it + 1 < NK) gload((it + 1) * BK);
        const int buf = it & 1;
#pragma unroll
        for (int kk = 0; kk < BK; kk += 8) {
            uint32_t af[4][4], bf[4][2];
#pragma unroll
            for (int mi = 0; mi < 4; mi++) {
                int r = wm * 64 + mi * 16 + g;
                af[mi][0] = As[buf][kk + tg][r];
                af[mi][1] = As[buf][kk + tg][r + 8];
                af[mi][2] = As[buf][kk + tg + 4][r];
                af[mi][3] = As[buf][kk + tg + 4][r + 8];
            }
#pragma unroll
            for (int ni = 0; ni < 4; ni++) {
                int c = wn * 32 + ni * 8 + g;
                bf[ni][0] = Bs[buf][kk + tg][c];
                bf[ni][1] = Bs[buf][kk + tg + 4][c];
            }
#pragma unroll
            for (int mi = 0; mi < 4; mi++)
#pragma unroll
                for (int ni = 0; ni < 4; ni++)
                    mma16n8k8(acc[mi][ni], af[mi], bf[ni]);
        }
        if (it + 1 < NK) {
            sstore((it + 1) & 1);
            __syncthreads();
        }
    }

    // epilogue
#pragma unroll
    for (int mi = 0; mi < 4; mi++) {
        long long r = row0 + wm * 64 + mi * 16 + g;
#pragma unroll
        for (int ni = 0; ni < 4; ni++) {
            long long c = col0 + wn * 32 + ni * 8 + tg * 2;
            float2 v0, v1;
            v0.x = acc[mi][ni][0] * alpha;  v0.y = acc[mi][ni][1] * alpha;
            v1.x = acc[mi][ni][2] * alpha;  v1.y = acc[mi][ni][3] * alpha;
            long long i0 = r * ldc + c;
            long long i1 = (r + 8) * ldc + c;
            if (Rp) {
                float2 r0 = *(const float2*)(Rp + i0);
                float2 r1 = *(const float2*)(Rp + i1);
                v0.x += r0.x; v0.y += r0.y;
                v1.x += r1.x; v1.y += r1.y;
            }
            *(float2*)(C + i0) = v0;
            *(float2*)(C + i1) = v1;
        }
    }
}

// ---------------------------------------------------------------------------
// Aux kernels
// ---------------------------------------------------------------------------
__global__ void embed_kernel(const int* __restrict__ ids,
                             const float* __restrict__ embed, float* __restrict__ h)
{
    int bs = blockIdx.x;
    long long tok = ids[bs];
    const float4* src = (const float4*)(embed + tok * DIM);
    float4* dst = (float4*)(h + (long long)bs * DIM);
    dst[threadIdx.x] = src[threadIdx.x];
}

__global__ void rope_kernel(float* __restrict__ qkv)
{
    int bs = blockIdx.x;
    int s  = bs & (SEQ - 1);
    int d  = threadIdx.x;                      // 0..511
    float freq = expf(-logf(10000.0f) * ((float)d / 512.0f));
    float sn, cs;
    sincosf((float)s * freq, &sn, &cs);

    float* rq = qkv + (long long)bs * 3072;
    float x1 = rq[d], x2 = rq[d + 512];
    rq[d]       = x1 * cs - x2 * sn;
    rq[d + 512] = x2 * cs + x1 * sn;

    float* rk = rq + 1024;
    x1 = rk[d]; x2 = rk[d + 512];
    rk[d]       = x1 * cs - x2 * sn;
    rk[d + 512] = x2 * cs + x1 * sn;
}

__global__ void transpose_v_kernel(const float* __restrict__ qkv, float* __restrict__ vt)
{
    __shared__ float t[32][33];
    int b = blockIdx.z;
    int s0 = blockIdx.x * 32, d0 = blockIdx.y * 32;
    int s = s0 + threadIdx.y, d = d0 + threadIdx.x;
    t[threadIdx.y][threadIdx.x] = qkv[((long long)b * SEQ + s) * 3072 + 2048 + d];
    __syncthreads();
    int dd = d0 + threadIdx.y, ss = s0 + threadIdx.x;
    vt[((long long)b * DIM + dd) * SEQ + ss] = t[threadIdx.x][threadIdx.y];
}

__global__ void softmax_kernel(float* __restrict__ Sm)
{
    __shared__ float red[256];
    float* row = Sm + (long long)blockIdx.x * SEQ;
    int t = threadIdx.x;
    float4 v = ((float4*)row)[t];
    float m = fmaxf(fmaxf(v.x, v.y), fmaxf(v.z, v.w));
    red[t] = m; __syncthreads();
    for (int w = 128; w > 0; w >>= 1) { if (t < w) red[t] = fmaxf(red[t], red[t + w]); __syncthreads(); }
    m = red[0]; __syncthreads();
    float e0 = expf(v.x - m), e1 = expf(v.y - m), e2 = expf(v.z - m), e3 = expf(v.w - m);
    red[t] = e0 + e1 + e2 + e3; __syncthreads();
    for (int w = 128; w > 0; w >>= 1) { if (t < w) red[t] += red[t + w]; __syncthreads(); }
    float inv = 1.0f / red[0];
    ((float4*)row)[t] = make_float4(e0 * inv, e1 * inv, e2 * inv, e3 * inv);
}

__global__ void silu_mul_kernel(const float* __restrict__ gu, float* __restrict__ t)
{
    long long i = (long long)blockIdx.x * blockDim.x + threadIdx.x;
    long long row = i >> 12;
    int col = (int)(i & 4095);
    float x = gu[row * 8192 + col];
    float u = gu[row * 8192 + 4096 + col];
    t[i] = x / (1.0f + expf(-x)) * u;
}

// ---------------------------------------------------------------------------
// Host side
// ---------------------------------------------------------------------------
static void gemm(const float* A, int lda, long long sAz,
                 const float* B, int ldb, long long sBz,
                 float* C, int ldc, long long sCz,
                 const float* R, int M, int N, int K, float alpha, int bz)
{
    dim3 grid(N / BN, M / BM, bz);
    tf32_gemm<<<grid, 256>>>(A, lda, sAz, B, ldb, sBz, C, ldc, sCz, R, K, alpha);
}

extern "C" void kernel_launch(void* const* d_in, const int* in_sizes, int n_in,
                              void* d_out, int out_size)
{
    (void)in_sizes; (void)n_in; (void)out_size;
    const int*   ids    = (const int*)d_in[0];
    const float* blocks = (const float*)d_in[1];
    float*       out    = (float*)d_out;

    float *h, *qkv, *vt, *s, *a, *gu, *t;
    cudaGetSymbolAddress((void**)&h,   g_h);
    cudaGetSymbolAddress((void**)&qkv, g_qkv);
    cudaGetSymbolAddress((void**)&vt,  g_vt);
    cudaGetSymbolAddress((void**)&s,   g_s);
    cudaGetSymbolAddress((void**)&a,   g_a);
    cudaGetSymbolAddress((void**)&gu,  g_gu);
    cudaGetSymbolAddress((void**)&t,   g_t);

    const long long SD3 = (long long)SEQ * 3072;
    const long long SD  = (long long)SEQ * DIM;
    const long long SS  = (long long)SEQ * SEQ;

    embed_kernel<<<MTOK, 256>>>(ids, blocks, h);

    for (int l = 0; l < 2; l++) {
        const float* Wqkv = blocks + LAYER0_OFF + (long long)l * LAYER_STRIDE; // [3072,1024]
        const float* Wo   = Wqkv + 3LL * DIM * DIM;
        const float* Wgu  = Wo + (long long)DIM * DIM;                          // [8192,1024]
        const float* Wd   = Wgu + 2LL * FFDIM * DIM;

        // qkv = h @ Wqkv^T (fused q|k|v)
        gemm(h, DIM, 0, Wqkv, DIM, 0, qkv, 3 * DIM, 0, nullptr, MTOK, 3 * DIM, DIM, 1.0f, 1);
        rope_kernel<<<MTOK, 512>>>(qkv);
        {
            dim3 gr(SEQ / 32, DIM / 32, BATCH);
            transpose_v_kernel<<<gr, dim3(32, 32)>>>(qkv, vt);
        }
        // scores = scale * q @ k^T (batched)
        gemm(qkv, 3 * DIM, SD3, qkv + DIM, 3 * DIM, SD3, s, SEQ, SS,
             nullptr, SEQ, SEQ, DIM, 1.0f / 32.0f, BATCH);
        softmax_kernel<<<BATCH * SEQ, 256>>>(s);
        // a = attn @ V (NT vs transposed V, batched)
        gemm(s, SEQ, SS, vt, SEQ, SD, a, DIM, SD, nullptr, SEQ, DIM, SEQ, 1.0f, BATCH);
        // h = a @ Wo^T + h
        gemm(a, DIM, 0, Wo, DIM, 0, h, DIM, 0, h, MTOK, DIM, DIM, 1.0f, 1);
        // gu = h @ [Wg|Wu]^T (fused)
        gemm(h, DIM, 0, Wgu, DIM, 0, gu, 2 * FFDIM, 0, nullptr, MTOK, 2 * FFDIM, DIM, 1.0f, 1);
        silu_mul_kernel<<<(MTOK * FFDIM) / 256, 256>>>(gu, t);
        // h = t @ Wd^T + h
        gemm(t, FFDIM, 0, Wd, FFDIM, 0, h, DIM, 0, h, MTOK, DIM, FFDIM, 1.0f, 1);
    }

    gemm(h, DIM, 0, blocks + OFF_LM, DIM, 0, out, VOC, 0, nullptr, MTOK, VOC, DIM, 1.0f, 1);
}